// round 2
// baseline (speedup 1.0000x reference)
#include <cuda_runtime.h>

// Problem constants
#define NN   50000
#define EE   800000
#define FE   16
#define RR   4
#define HH   4
#define CC   32
#define HC   128

// ---------------- scratch (static device globals; no allocation) ----------------
__device__ __align__(16) float g_xw[RR * NN * HC];   // per-relation projections (102.4MB)
__device__ __align__(16) float g_h[NN * HC];         // layer-1 output (relu)
__device__ __align__(16) float g_qn[RR * NN * HH];   // per-node query logits [r][n][4]
__device__ __align__(16) float g_kn[RR * NN * HH];   // per-node key logits   [r][n][4]
__device__ __align__(16) float g_ea1[EE * HH];       // edge_attr @ (le1@e1)  [e][4]
__device__ __align__(16) float g_ea3[EE * HH];       // edge_attr @ (le3@e3)  [e][4]
__device__ int   g_deg[NN];
__device__ int   g_rowstart[NN + 1];
__device__ int   g_cursor[NN];
__device__ int2  g_csr[EE];                          // { (et<<16)|src , eid } sorted by dst
__device__ float g_M1[FE * HH];
__device__ float g_M3[FE * HH];
__device__ __align__(16) float g_wt[RR * HC * HC];   // W transposed: [r][c][k]
__device__ __align__(16) float g_wqk[RR * HC * 8];   // folded (W@q | W@k): [r][f][8]

// packed f32x2 FMA: d.lo += a.lo*b.lo ; d.hi += a.hi*b.hi
#define FMA2(d, a, b) asm("fma.rn.f32x2 %0, %1, %2, %0;" : "+l"(d) : "l"(a), "l"(b))

// ---------------- CSR build ----------------
__global__ void k_zero_deg() {
    int i = blockIdx.x * blockDim.x + threadIdx.x;
    if (i < NN) g_deg[i] = 0;
}

__global__ void k_hist(const int* __restrict__ ei) {
    int e = blockIdx.x * blockDim.x + threadIdx.x;
    if (e < EE) atomicAdd(&g_deg[ei[EE + e]], 1);
}

// single-block exclusive scan of g_deg -> g_rowstart / g_cursor
__global__ void k_scan() {
    __shared__ int sm[1024];
    __shared__ int s_carry;
    int tid = threadIdx.x;
    if (tid == 0) s_carry = 0;
    __syncthreads();
    const int TILES = (NN + 8191) / 8192;   // 7
    for (int tile = 0; tile < TILES; tile++) {
        int base = tile * 8192 + tid * 8;
        int v[8];
        int tsum = 0;
#pragma unroll
        for (int j = 0; j < 8; j++) {
            int idx = base + j;
            v[j] = (idx < NN) ? g_deg[idx] : 0;
            tsum += v[j];
        }
        sm[tid] = tsum;
        __syncthreads();
        for (int off = 1; off < 1024; off <<= 1) {
            int t = (tid >= off) ? sm[tid - off] : 0;
            __syncthreads();
            sm[tid] += t;
            __syncthreads();
        }
        int excl = s_carry + sm[tid] - tsum;
        int run = excl;
#pragma unroll
        for (int j = 0; j < 8; j++) {
            int idx = base + j;
            if (idx < NN) { g_rowstart[idx] = run; g_cursor[idx] = run; }
            run += v[j];
        }
        __syncthreads();
        if (tid == 0) s_carry += sm[1023];
        __syncthreads();
    }
    if (tid == 0) g_rowstart[NN] = s_carry;
}

__global__ void k_scatter(const int* __restrict__ ei, const int* __restrict__ etype) {
    int e = blockIdx.x * blockDim.x + threadIdx.x;
    if (e >= EE) return;
    int d = ei[EE + e];
    int s = ei[e];
    int t = etype[e];
    int pos = atomicAdd(&g_cursor[d], 1);
    g_csr[pos] = make_int2((t << 16) | s, e);
}

// ---------------- W transpose: g_wt[r][c][k] = w[r][k][c] ----------------
__global__ void k_wt(const float* __restrict__ w) {
    int idx = blockIdx.x * 256 + threadIdx.x;
    if (idx < RR * HC * HC) {
        int r = idx >> 14;
        int rem = idx & 16383;
        int k = rem >> 7, c = rem & 127;
        g_wt[(r << 14) + (c << 7) + k] = w[idx];
    }
}

// ---------------- folded q/k: g_wqk[r][f][0:4]=W_r@q, [4:8]=W_r@k ----------------
__global__ void k_wqk(const float* __restrict__ w, const float* __restrict__ q,
                      const float* __restrict__ k) {
    int idx = blockIdx.x * 256 + threadIdx.x;    // 4096 total
    if (idx >= RR * HC * 8) return;
    int r = idx >> 10;
    int f = (idx >> 3) & 127;
    int o = idx & 7;
    const float* vec = (o < 4) ? q : k;
    int h = o & 3;
    const float* wrow = w + (r << 14) + (f << 7);
    float s = 0.f;
#pragma unroll 8
    for (int c = 0; c < HC; c++) s += wrow[c] * vec[c * 4 + h];
    g_wqk[idx] = s;
}

// ---------------- M = le @ e  (16x4, both layers) ----------------
__global__ void k_M(const float* __restrict__ le1, const float* __restrict__ e1,
                    const float* __restrict__ le3, const float* __restrict__ e3) {
    int t = threadIdx.x;
    if (t < 64) {
        int f = t >> 2, h = t & 3;
        float s = 0.f;
        for (int c = 0; c < HC; c++) s += le1[f * HC + c] * e1[c * HH + h];
        g_M1[t] = s;
    } else if (t < 128) {
        int u = t - 64;
        int f = u >> 2, h = u & 3;
        float s = 0.f;
        for (int c = 0; c < HC; c++) s += le3[f * HC + c] * e3[c * HH + h];
        g_M3[u] = s;
    }
}

// ---------------- ea = edge_attr @ M  (both layers in one pass) ----------------
__global__ void k_ea(const float* __restrict__ eattr) {
    __shared__ float sM1[64], sM3[64];
    if (threadIdx.x < 64) sM1[threadIdx.x] = g_M1[threadIdx.x];
    else if (threadIdx.x < 128) sM3[threadIdx.x - 64] = g_M3[threadIdx.x - 64];
    __syncthreads();
    int e = blockIdx.x * blockDim.x + threadIdx.x;
    if (e >= EE) return;
    const float* a = eattr + (size_t)e * FE;
    float r1[4] = {0, 0, 0, 0}, r3[4] = {0, 0, 0, 0};
#pragma unroll
    for (int f = 0; f < FE; f++) {
        float v = a[f];
        r1[0] += v * sM1[f * 4 + 0]; r1[1] += v * sM1[f * 4 + 1];
        r1[2] += v * sM1[f * 4 + 2]; r1[3] += v * sM1[f * 4 + 3];
        r3[0] += v * sM3[f * 4 + 0]; r3[1] += v * sM3[f * 4 + 1];
        r3[2] += v * sM3[f * 4 + 2]; r3[3] += v * sM3[f * 4 + 3];
    }
    *(float4*)&g_ea1[(size_t)e * 4] = make_float4(r1[0], r1[1], r1[2], r1[3]);
    *(float4*)&g_ea3[(size_t)e * 4] = make_float4(r3[0], r3[1], r3[2], r3[3]);
}

// ---------------- batched GEMM via packed f32x2 FMA ----------------
// xw[r] = X @ W[r].  X:[N,128] tile in smem row-major; W from g_wt[r][c][k] so
// (k,k+1) pairs are contiguous.  f32x2 lanes hold even/odd-K partial sums.
__global__ void k_gemm2(const float* __restrict__ xin_arg, int layer) {
    __shared__ __align__(16) float xs[64 * 128];
    const float* xin = (layer == 1) ? xin_arg : g_h;
    int r = blockIdx.y;
    int i0 = blockIdx.x * 64;
    int tid = threadIdx.x;
#pragma unroll
    for (int it = 0; it < 8; it++) {
        int q = tid + it * 256;          // float4 index within 64x128 tile
        int row = q >> 5, c4 = q & 31;
        float4 v = make_float4(0.f, 0.f, 0.f, 0.f);
        int gr = i0 + row;
        if (gr < NN) v = *(const float4*)(xin + (size_t)gr * 128 + c4 * 4);
        *(float4*)&xs[row * 128 + c4 * 4] = v;
    }
    __syncthreads();
    int ct = tid & 31, rt = tid >> 5;
    const unsigned long long* wt =
        (const unsigned long long*)g_wt + (size_t)r * 8192;   // [c][kk] pairs
    const unsigned long long* xsp = (const unsigned long long*)xs;  // [row][kk]

    unsigned long long accp[8][4];
#pragma unroll
    for (int i = 0; i < 8; i++)
#pragma unroll
        for (int j = 0; j < 4; j++) accp[i][j] = 0ULL;

#pragma unroll 4
    for (int kk = 0; kk < 64; kk++) {
        unsigned long long w0 = wt[(ct * 4 + 0) * 64 + kk];
        unsigned long long w1 = wt[(ct * 4 + 1) * 64 + kk];
        unsigned long long w2 = wt[(ct * 4 + 2) * 64 + kk];
        unsigned long long w3 = wt[(ct * 4 + 3) * 64 + kk];
#pragma unroll
        for (int i = 0; i < 8; i++) {
            unsigned long long xv = xsp[(rt * 8 + i) * 64 + kk];
            FMA2(accp[i][0], xv, w0);
            FMA2(accp[i][1], xv, w1);
            FMA2(accp[i][2], xv, w2);
            FMA2(accp[i][3], xv, w3);
        }
    }

    union U { unsigned long long u; float2 f; };
#pragma unroll
    for (int i = 0; i < 8; i++) {
        int gr = i0 + rt * 8 + i;
        if (gr < NN) {
            U u0, u1, u2, u3;
            u0.u = accp[i][0]; u1.u = accp[i][1];
            u2.u = accp[i][2]; u3.u = accp[i][3];
            *(float4*)&g_xw[((size_t)r * NN + gr) * 128 + ct * 4] =
                make_float4(u0.f.x + u0.f.y, u1.f.x + u1.f.y,
                            u2.f.x + u2.f.y, u3.f.x + u3.f.y);
        }
    }
}

// ---------------- qn/kn = x @ g_wqk (node-parallel, reads x not g_xw) ----------------
// block 256 thr, 32 nodes/block.  warp w handles (relation w>>1, q-or-k w&1).
__global__ void k_qkx(const float* __restrict__ xin_arg, int layer) {
    __shared__ float xs2[32 * 129];          // padded, conflict-free across nodes
    __shared__ __align__(16) float sw[RR * HC * 8];
    const float* xin = (layer == 1) ? xin_arg : g_h;
    int tid = threadIdx.x;
    int n0 = blockIdx.x * 32;
    // load x tile
#pragma unroll
    for (int it = 0; it < 4; it++) {
        int q = tid + it * 256;              // float4 index over 32x128
        int row = q >> 5, c4 = q & 31;
        float4 v = make_float4(0.f, 0.f, 0.f, 0.f);
        int gn = n0 + row;
        if (gn < NN) v = *(const float4*)(xin + (size_t)gn * 128 + c4 * 4);
        xs2[row * 129 + c4 * 4 + 0] = v.x;
        xs2[row * 129 + c4 * 4 + 1] = v.y;
        xs2[row * 129 + c4 * 4 + 2] = v.z;
        xs2[row * 129 + c4 * 4 + 3] = v.w;
    }
    // load folded weights
#pragma unroll
    for (int it = 0; it < 16; it++) sw[tid + it * 256] = g_wqk[tid + it * 256];
    __syncthreads();

    int nd = tid & 31;
    int slot = tid >> 5;                     // 0..7
    int r = slot >> 1;
    int half = slot & 1;                     // 0 = q heads, 1 = k heads
    int n = n0 + nd;
    if (n >= NN) return;

    float s0 = 0.f, s1 = 0.f, s2 = 0.f, s3 = 0.f;
#pragma unroll 8
    for (int k = 0; k < HC; k++) {
        float xv = xs2[nd * 129 + k];
        float4 wv = *(const float4*)&sw[(r * HC + k) * 8 + half * 4];
        s0 += xv * wv.x; s1 += xv * wv.y; s2 += xv * wv.z; s3 += xv * wv.w;
    }
    float* dst = (half == 0) ? g_qn : g_kn;
    *(float4*)&dst[((size_t)r * NN + n) * 4] = make_float4(s0, s1, s2, s3);
}

// ---------------- single-pass softmax + aggregation: warp per dst node ----------------
// Softmax is shift-invariant; logits here are O(1), so no max pass is needed.
__global__ void k_agg(const float* __restrict__ bias, float* __restrict__ out, int layer) {
    int n = (blockIdx.x * blockDim.x + threadIdx.x) >> 5;
    int lane = threadIdx.x & 31;
    if (n >= NN) return;
    const float* ea = (layer == 1) ? g_ea1 : g_ea3;
    int rs = g_rowstart[n], re = g_rowstart[n + 1];

    float4 qi[4];
#pragma unroll
    for (int r = 0; r < 4; r++) qi[r] = *(const float4*)&g_qn[((size_t)r * NN + n) * 4];

    float s0 = 0.f, s1 = 0.f, s2 = 0.f, s3 = 0.f;
    float acc0 = 0.f, acc1 = 0.f, acc2 = 0.f, acc3 = 0.f;
    for (int e = rs; e < re; e++) {
        int2 rec = g_csr[e];
        int et = rec.x >> 16, src = rec.x & 0xFFFF;
        float4 kv = *(const float4*)&g_kn[((size_t)et * NN + src) * 4];
        float4 ev = *(const float4*)&ea[(size_t)rec.y * 4];
        float a0 = qi[et].x + kv.x + ev.x; a0 = a0 > 0.f ? a0 : 0.2f * a0;
        float a1 = qi[et].y + kv.y + ev.y; a1 = a1 > 0.f ? a1 : 0.2f * a1;
        float a2 = qi[et].z + kv.z + ev.z; a2 = a2 > 0.f ? a2 : 0.2f * a2;
        float a3 = qi[et].w + kv.w + ev.w; a3 = a3 > 0.f ? a3 : 0.2f * a3;
        float p0 = __expf(a0), p1 = __expf(a1);
        float p2 = __expf(a2), p3 = __expf(a3);
        s0 += p0; s1 += p1; s2 += p2; s3 += p3;
        const float* xr = g_xw + ((size_t)et * NN + src) * 128 + lane;
        acc0 += p0 * xr[0];
        acc1 += p1 * xr[32];
        acc2 += p2 * xr[64];
        acc3 += p3 * xr[96];
    }

    const float EPS = 1e-16f;
    if (layer == 1) {
        float v0 = acc0 / (s0 + EPS) + bias[lane];
        float v1 = acc1 / (s1 + EPS) + bias[lane + 32];
        float v2 = acc2 / (s2 + EPS) + bias[lane + 64];
        float v3 = acc3 / (s3 + EPS) + bias[lane + 96];
        float* hp = g_h + (size_t)n * 128 + lane;
        hp[0]  = v0 > 0.f ? v0 : 0.f;
        hp[32] = v1 > 0.f ? v1 : 0.f;
        hp[64] = v2 > 0.f ? v2 : 0.f;
        hp[96] = v3 > 0.f ? v3 : 0.f;
    } else {
        float v = 0.25f * (acc0 / (s0 + EPS) + acc1 / (s1 + EPS) +
                           acc2 / (s2 + EPS) + acc3 / (s3 + EPS)) + bias[lane];
        out[(size_t)n * 32 + lane] = v;
    }
}

// ---------------- launch ----------------
extern "C" void kernel_launch(void* const* d_in, const int* in_sizes, int n_in,
                              void* d_out, int out_size) {
    const float* x     = (const float*)d_in[0];
    const int*   ei    = (const int*)  d_in[1];
    const float* eattr = (const float*)d_in[2];
    const int*   etype = (const int*)  d_in[3];
    const float* w1  = (const float*)d_in[4];
    const float* q1  = (const float*)d_in[5];
    const float* k1  = (const float*)d_in[6];
    const float* e1  = (const float*)d_in[7];
    const float* le1 = (const float*)d_in[8];
    const float* b1  = (const float*)d_in[9];
    const float* w3  = (const float*)d_in[10];
    const float* q3  = (const float*)d_in[11];
    const float* k3  = (const float*)d_in[12];
    const float* e3  = (const float*)d_in[13];
    const float* le3 = (const float*)d_in[14];
    const float* b3  = (const float*)d_in[15];
    float* out = (float*)d_out;

    const int EB = (EE + 255) / 256;         // 3125
    const int NB = (NN + 255) / 256;         // 196
    const int WT_B = (RR * HC * HC + 255) / 256;   // 256
    const int QKX_B = (NN + 31) / 32;        // 1563

    // ordered so the heavy GEMM lands at the launch index ncu samples
    k_zero_deg<<<NB, 256>>>();                             // 0
    k_hist<<<EB, 256>>>(ei);                               // 1
    k_wt<<<WT_B, 256>>>(w1);                               // 2
    k_gemm2<<<dim3((NN + 63) / 64, RR), 256>>>(x, 1);      // 3  <- profile target
    k_scan<<<1, 1024>>>();                                 // 4
    k_scatter<<<EB, 256>>>(ei, etype);                     // 5
    k_M<<<1, 128>>>(le1, e1, le3, e3);                     // 6
    k_ea<<<EB, 256>>>(eattr);                              // 7
    k_wqk<<<16, 256>>>(w1, q1, k1);                        // 8
    k_qkx<<<QKX_B, 256>>>(x, 1);                           // 9
    k_agg<<<(NN + 7) / 8, 256>>>(b1, out, 1);              // 10

    k_wt<<<WT_B, 256>>>(w3);                               // 11
    k_gemm2<<<dim3((NN + 63) / 64, RR), 256>>>(x, 2);      // 12
    k_wqk<<<16, 256>>>(w3, q3, k3);                        // 13
    k_qkx<<<QKX_B, 256>>>(x, 2);                           // 14
    k_agg<<<(NN + 7) / 8, 256>>>(b3, out, 2);              // 15
}

// round 3
// speedup vs baseline: 1.8185x; 1.8185x over previous
#include <cuda_runtime.h>

// Problem constants
#define NN   50000
#define EE   800000
#define FE   16
#define RR   4
#define HH   4
#define CC   32
#define HC   128

// ---------------- scratch (static device globals; no allocation) ----------------
__device__ __align__(16) float g_xw[RR * NN * HC];   // per-relation projections (102.4MB)
__device__ __align__(16) float g_h[NN * HC];         // layer-1 output (relu)
__device__ __align__(16) float g_qn[RR * NN * HH];   // per-node query logits [r][n][4]
__device__ __align__(16) float g_kn[RR * NN * HH];   // per-node key logits   [r][n][4]
__device__ __align__(16) float g_ea1[EE * HH];       // edge_attr @ (le1@e1)  [e][4]
__device__ __align__(16) float g_ea3[EE * HH];       // edge_attr @ (le3@e3)  [e][4]
__device__ int   g_deg[NN];
__device__ int   g_rowstart[NN + 1];
__device__ int   g_cursor[NN];
__device__ int2  g_csr[EE];                          // { (et<<16)|src , eid } sorted by dst
__device__ float g_M1[FE * HH];
__device__ float g_M3[FE * HH];
// W pair-packed: g_wp[r][kk][c] = (w[r][2kk][c], w[r][2kk+1][c]) ; c contiguous -> coalesced
__device__ __align__(16) float2 g_wp[RR * (HC / 2) * HC];
__device__ __align__(16) float g_wqk[RR * HC * 8];   // folded (W@q | W@k): [r][f][8]

// packed f32x2 FMA: d.lo += a.lo*b.lo ; d.hi += a.hi*b.hi
#define FMA2(d, a, b) asm("fma.rn.f32x2 %0, %1, %2, %0;" : "+l"(d) : "l"(a), "l"(b))

// ---------------- CSR build ----------------
__global__ void k_zero_deg() {
    int i = blockIdx.x * blockDim.x + threadIdx.x;
    if (i < NN) g_deg[i] = 0;
}

__global__ void k_hist(const int* __restrict__ ei) {
    int e = blockIdx.x * blockDim.x + threadIdx.x;
    if (e < EE) atomicAdd(&g_deg[ei[EE + e]], 1);
}

// single-block exclusive scan of g_deg -> g_rowstart / g_cursor
__global__ void k_scan() {
    __shared__ int sm[1024];
    __shared__ int s_carry;
    int tid = threadIdx.x;
    if (tid == 0) s_carry = 0;
    __syncthreads();
    const int TILES = (NN + 8191) / 8192;   // 7
    for (int tile = 0; tile < TILES; tile++) {
        int base = tile * 8192 + tid * 8;
        int v[8];
        int tsum = 0;
#pragma unroll
        for (int j = 0; j < 8; j++) {
            int idx = base + j;
            v[j] = (idx < NN) ? g_deg[idx] : 0;
            tsum += v[j];
        }
        sm[tid] = tsum;
        __syncthreads();
        for (int off = 1; off < 1024; off <<= 1) {
            int t = (tid >= off) ? sm[tid - off] : 0;
            __syncthreads();
            sm[tid] += t;
            __syncthreads();
        }
        int excl = s_carry + sm[tid] - tsum;
        int run = excl;
#pragma unroll
        for (int j = 0; j < 8; j++) {
            int idx = base + j;
            if (idx < NN) { g_rowstart[idx] = run; g_cursor[idx] = run; }
            run += v[j];
        }
        __syncthreads();
        if (tid == 0) s_carry += sm[1023];
        __syncthreads();
    }
    if (tid == 0) g_rowstart[NN] = s_carry;
}

__global__ void k_scatter(const int* __restrict__ ei, const int* __restrict__ etype) {
    int e = blockIdx.x * blockDim.x + threadIdx.x;
    if (e >= EE) return;
    int d = ei[EE + e];
    int s = ei[e];
    int t = etype[e];
    int pos = atomicAdd(&g_cursor[d], 1);
    g_csr[pos] = make_int2((t << 16) | s, e);
}

// ---------------- W pair-pack: g_wp[r][kk][c] = (w[r][2kk][c], w[r][2kk+1][c]) ----------------
__global__ void k_wp(const float* __restrict__ w) {
    int idx = blockIdx.x * 256 + threadIdx.x;          // over RR*64*128 = 32768
    if (idx >= RR * (HC / 2) * HC) return;
    int r = idx >> 13;
    int rem = idx & 8191;
    int kk = rem >> 7, c = rem & 127;
    const float* wr = w + ((size_t)r << 14);
    g_wp[idx] = make_float2(wr[(2 * kk) * 128 + c], wr[(2 * kk + 1) * 128 + c]);
}

// ---------------- folded q/k: g_wqk[r][f][0:4]=W_r@q, [4:8]=W_r@k ----------------
__global__ void k_wqk(const float* __restrict__ w, const float* __restrict__ q,
                      const float* __restrict__ k) {
    int idx = blockIdx.x * 256 + threadIdx.x;    // 4096 total
    if (idx >= RR * HC * 8) return;
    int r = idx >> 10;
    int f = (idx >> 3) & 127;
    int o = idx & 7;
    const float* vec = (o < 4) ? q : k;
    int h = o & 3;
    const float* wrow = w + (r << 14) + (f << 7);
    float s = 0.f;
#pragma unroll 8
    for (int c = 0; c < HC; c++) s += wrow[c] * vec[c * 4 + h];
    g_wqk[idx] = s;
}

// ---------------- M = le @ e  (16x4, both layers) ----------------
__global__ void k_M(const float* __restrict__ le1, const float* __restrict__ e1,
                    const float* __restrict__ le3, const float* __restrict__ e3) {
    int t = threadIdx.x;
    if (t < 64) {
        int f = t >> 2, h = t & 3;
        float s = 0.f;
        for (int c = 0; c < HC; c++) s += le1[f * HC + c] * e1[c * HH + h];
        g_M1[t] = s;
    } else if (t < 128) {
        int u = t - 64;
        int f = u >> 2, h = u & 3;
        float s = 0.f;
        for (int c = 0; c < HC; c++) s += le3[f * HC + c] * e3[c * HH + h];
        g_M3[u] = s;
    }
}

// ---------------- ea = edge_attr @ M  (both layers in one pass) ----------------
__global__ void k_ea(const float* __restrict__ eattr) {
    __shared__ float sM1[64], sM3[64];
    if (threadIdx.x < 64) sM1[threadIdx.x] = g_M1[threadIdx.x];
    else if (threadIdx.x < 128) sM3[threadIdx.x - 64] = g_M3[threadIdx.x - 64];
    __syncthreads();
    int e = blockIdx.x * blockDim.x + threadIdx.x;
    if (e >= EE) return;
    const float* a = eattr + (size_t)e * FE;
    float r1[4] = {0, 0, 0, 0}, r3[4] = {0, 0, 0, 0};
#pragma unroll
    for (int f = 0; f < FE; f++) {
        float v = a[f];
        r1[0] += v * sM1[f * 4 + 0]; r1[1] += v * sM1[f * 4 + 1];
        r1[2] += v * sM1[f * 4 + 2]; r1[3] += v * sM1[f * 4 + 3];
        r3[0] += v * sM3[f * 4 + 0]; r3[1] += v * sM3[f * 4 + 1];
        r3[2] += v * sM3[f * 4 + 2]; r3[3] += v * sM3[f * 4 + 3];
    }
    *(float4*)&g_ea1[(size_t)e * 4] = make_float4(r1[0], r1[1], r1[2], r1[3]);
    *(float4*)&g_ea3[(size_t)e * 4] = make_float4(r3[0], r3[1], r3[2], r3[3]);
}

// ---------------- batched GEMM via packed f32x2 FMA ----------------
// xw[r] = X @ W[r].  X:[N,128] 64-row tile in smem (broadcast LDS.64 of K-pairs);
// W from g_wp[r][kk][c] -> lane ct reads c=ct+32j: coalesced LDG.64, L1-resident.
// f32x2 lanes hold even/odd-K partial sums, reduced in the epilogue.
__global__ void __launch_bounds__(256, 2) k_gemm2(const float* __restrict__ xin_arg, int layer) {
    __shared__ __align__(16) float xs[64 * 128];       // 32 KB
    const float* xin = (layer == 1) ? xin_arg : g_h;
    int r = blockIdx.y;
    int i0 = blockIdx.x * 64;
    int tid = threadIdx.x;
#pragma unroll
    for (int it = 0; it < 8; it++) {
        int q = tid + it * 256;          // float4 index within 64x128 tile
        int row = q >> 5, c4 = q & 31;
        float4 v = make_float4(0.f, 0.f, 0.f, 0.f);
        int gr = i0 + row;
        if (gr < NN) v = *(const float4*)(xin + (size_t)gr * 128 + c4 * 4);
        *(float4*)&xs[row * 128 + c4 * 4] = v;
    }
    __syncthreads();
    int ct = tid & 31, rt = tid >> 5;
    const unsigned long long* wp =
        (const unsigned long long*)g_wp + (size_t)r * (HC / 2) * HC;   // [kk][c]
    const unsigned long long* xsp = (const unsigned long long*)xs;     // [row][kk]

    unsigned long long accp[8][4];
#pragma unroll
    for (int i = 0; i < 8; i++)
#pragma unroll
        for (int j = 0; j < 4; j++) accp[i][j] = 0ULL;

#pragma unroll 2
    for (int kk = 0; kk < 64; kk++) {
        unsigned long long w0 = __ldg(&wp[kk * 128 + ct +  0]);
        unsigned long long w1 = __ldg(&wp[kk * 128 + ct + 32]);
        unsigned long long w2 = __ldg(&wp[kk * 128 + ct + 64]);
        unsigned long long w3 = __ldg(&wp[kk * 128 + ct + 96]);
#pragma unroll
        for (int i = 0; i < 8; i++) {
            unsigned long long xv = xsp[(rt * 8 + i) * 64 + kk];   // warp-uniform broadcast
            FMA2(accp[i][0], xv, w0);
            FMA2(accp[i][1], xv, w1);
            FMA2(accp[i][2], xv, w2);
            FMA2(accp[i][3], xv, w3);
        }
    }

    union U { unsigned long long u; float2 f; };
#pragma unroll
    for (int i = 0; i < 8; i++) {
        int gr = i0 + rt * 8 + i;
        if (gr < NN) {
            float* orow = &g_xw[((size_t)r * NN + gr) * 128];
#pragma unroll
            for (int j = 0; j < 4; j++) {
                U u; u.u = accp[i][j];
                orow[ct + 32 * j] = u.f.x + u.f.y;     // coalesced STG.32 across lanes
            }
        }
    }
}

// ---------------- qn/kn = x @ g_wqk (node-parallel, reads x not g_xw) ----------------
__global__ void k_qkx(const float* __restrict__ xin_arg, int layer) {
    __shared__ float xs2[32 * 129];          // padded, conflict-free across nodes
    __shared__ __align__(16) float sw[RR * HC * 8];
    const float* xin = (layer == 1) ? xin_arg : g_h;
    int tid = threadIdx.x;
    int n0 = blockIdx.x * 32;
#pragma unroll
    for (int it = 0; it < 4; it++) {
        int q = tid + it * 256;              // float4 index over 32x128
        int row = q >> 5, c4 = q & 31;
        float4 v = make_float4(0.f, 0.f, 0.f, 0.f);
        int gn = n0 + row;
        if (gn < NN) v = *(const float4*)(xin + (size_t)gn * 128 + c4 * 4);
        xs2[row * 129 + c4 * 4 + 0] = v.x;
        xs2[row * 129 + c4 * 4 + 1] = v.y;
        xs2[row * 129 + c4 * 4 + 2] = v.z;
        xs2[row * 129 + c4 * 4 + 3] = v.w;
    }
#pragma unroll
    for (int it = 0; it < 16; it++) sw[tid + it * 256] = g_wqk[tid + it * 256];
    __syncthreads();

    int nd = tid & 31;
    int slot = tid >> 5;                     // 0..7
    int r = slot >> 1;
    int half = slot & 1;                     // 0 = q heads, 1 = k heads
    int n = n0 + nd;
    if (n >= NN) return;

    float s0 = 0.f, s1 = 0.f, s2 = 0.f, s3 = 0.f;
#pragma unroll 8
    for (int k = 0; k < HC; k++) {
        float xv = xs2[nd * 129 + k];
        float4 wv = *(const float4*)&sw[(r * HC + k) * 8 + half * 4];
        s0 += xv * wv.x; s1 += xv * wv.y; s2 += xv * wv.z; s3 += xv * wv.w;
    }
    float* dst = (half == 0) ? g_qn : g_kn;
    *(float4*)&dst[((size_t)r * NN + n) * 4] = make_float4(s0, s1, s2, s3);
}

// ---------------- single-pass softmax + aggregation: warp per dst node ----------------
__global__ void k_agg(const float* __restrict__ bias, float* __restrict__ out, int layer) {
    int n = (blockIdx.x * blockDim.x + threadIdx.x) >> 5;
    int lane = threadIdx.x & 31;
    if (n >= NN) return;
    const float* ea = (layer == 1) ? g_ea1 : g_ea3;
    int rs = g_rowstart[n], re = g_rowstart[n + 1];

    float4 qi[4];
#pragma unroll
    for (int r = 0; r < 4; r++) qi[r] = *(const float4*)&g_qn[((size_t)r * NN + n) * 4];

    float s0 = 0.f, s1 = 0.f, s2 = 0.f, s3 = 0.f;
    float acc0 = 0.f, acc1 = 0.f, acc2 = 0.f, acc3 = 0.f;
    for (int e = rs; e < re; e++) {
        int2 rec = g_csr[e];
        int et = rec.x >> 16, src = rec.x & 0xFFFF;
        float4 kv = *(const float4*)&g_kn[((size_t)et * NN + src) * 4];
        float4 ev = *(const float4*)&ea[(size_t)rec.y * 4];
        float a0 = qi[et].x + kv.x + ev.x; a0 = a0 > 0.f ? a0 : 0.2f * a0;
        float a1 = qi[et].y + kv.y + ev.y; a1 = a1 > 0.f ? a1 : 0.2f * a1;
        float a2 = qi[et].z + kv.z + ev.z; a2 = a2 > 0.f ? a2 : 0.2f * a2;
        float a3 = qi[et].w + kv.w + ev.w; a3 = a3 > 0.f ? a3 : 0.2f * a3;
        float p0 = __expf(a0), p1 = __expf(a1);
        float p2 = __expf(a2), p3 = __expf(a3);
        s0 += p0; s1 += p1; s2 += p2; s3 += p3;
        const float* xr = g_xw + ((size_t)et * NN + src) * 128 + lane;
        acc0 += p0 * xr[0];
        acc1 += p1 * xr[32];
        acc2 += p2 * xr[64];
        acc3 += p3 * xr[96];
    }

    const float EPS = 1e-16f;
    if (layer == 1) {
        float v0 = acc0 / (s0 + EPS) + bias[lane];
        float v1 = acc1 / (s1 + EPS) + bias[lane + 32];
        float v2 = acc2 / (s2 + EPS) + bias[lane + 64];
        float v3 = acc3 / (s3 + EPS) + bias[lane + 96];
        float* hp = g_h + (size_t)n * 128 + lane;
        hp[0]  = v0 > 0.f ? v0 : 0.f;
        hp[32] = v1 > 0.f ? v1 : 0.f;
        hp[64] = v2 > 0.f ? v2 : 0.f;
        hp[96] = v3 > 0.f ? v3 : 0.f;
    } else {
        float v = 0.25f * (acc0 / (s0 + EPS) + acc1 / (s1 + EPS) +
                           acc2 / (s2 + EPS) + acc3 / (s3 + EPS)) + bias[lane];
        out[(size_t)n * 32 + lane] = v;
    }
}

// ---------------- launch ----------------
extern "C" void kernel_launch(void* const* d_in, const int* in_sizes, int n_in,
                              void* d_out, int out_size) {
    const float* x     = (const float*)d_in[0];
    const int*   ei    = (const int*)  d_in[1];
    const float* eattr = (const float*)d_in[2];
    const int*   etype = (const int*)  d_in[3];
    const float* w1  = (const float*)d_in[4];
    const float* q1  = (const float*)d_in[5];
    const float* k1  = (const float*)d_in[6];
    const float* e1  = (const float*)d_in[7];
    const float* le1 = (const float*)d_in[8];
    const float* b1  = (const float*)d_in[9];
    const float* w3  = (const float*)d_in[10];
    const float* q3  = (const float*)d_in[11];
    const float* k3  = (const float*)d_in[12];
    const float* e3  = (const float*)d_in[13];
    const float* le3 = (const float*)d_in[14];
    const float* b3  = (const float*)d_in[15];
    float* out = (float*)d_out;

    const int EB = (EE + 255) / 256;         // 3125
    const int NB = (NN + 255) / 256;         // 196
    const int WP_B = (RR * (HC / 2) * HC + 255) / 256;   // 128
    const int QKX_B = (NN + 31) / 32;        // 1563

    // ordered so the heavy GEMM lands at the launch index ncu samples
    k_zero_deg<<<NB, 256>>>();                             // 0
    k_hist<<<EB, 256>>>(ei);                               // 1
    k_wp<<<WP_B, 256>>>(w1);                               // 2
    k_gemm2<<<dim3((NN + 63) / 64, RR), 256>>>(x, 1);      // 3  <- profile target
    k_scan<<<1, 1024>>>();                                 // 4
    k_scatter<<<EB, 256>>>(ei, etype);                     // 5
    k_M<<<1, 128>>>(le1, e1, le3, e3);                     // 6
    k_ea<<<EB, 256>>>(eattr);                              // 7
    k_wqk<<<16, 256>>>(w1, q1, k1);                        // 8
    k_qkx<<<QKX_B, 256>>>(x, 1);                           // 9
    k_agg<<<(NN + 7) / 8, 256>>>(b1, out, 1);              // 10

    k_wp<<<WP_B, 256>>>(w3);                               // 11
    k_gemm2<<<dim3((NN + 63) / 64, RR), 256>>>(x, 2);      // 12
    k_wqk<<<16, 256>>>(w3, q3, k3);                        // 13
    k_qkx<<<QKX_B, 256>>>(x, 2);                           // 14
    k_agg<<<(NN + 7) / 8, 256>>>(b3, out, 2);              // 15
}

// round 4
// speedup vs baseline: 1.9884x; 1.0934x over previous
#include <cuda_runtime.h>

// Problem constants
#define NN   50000
#define EE   800000
#define FE   16
#define RR   4
#define HH   4
#define CC   32
#define HC   128

// ---------------- scratch (static device globals; no allocation) ----------------
__device__ __align__(16) float g_xw[RR * NN * HC];   // per-relation projections (102.4MB)
__device__ __align__(16) float g_h[NN * HC];         // layer-1 output (relu)
__device__ __align__(16) float g_qn[RR * NN * HH];   // per-node query logits [r][n][4]
__device__ __align__(16) float g_kn[RR * NN * HH];   // per-node key logits   [r][n][4]
__device__ __align__(16) float4 g_p[EE];             // per-edge attention probs (unnorm)
__device__ int   g_deg[NN];
__device__ int   g_rowstart[NN + 1];
__device__ int   g_cursor[NN];
__device__ int2  g_csr[EE];                          // { (et<<16)|src , eid } sorted by dst
__device__ float g_M1[FE * HH];
__device__ float g_M3[FE * HH];
// W col-pair+K-pair packed: g_wp4[r][kk][cp] = (w[2kk][2cp], w[2kk+1][2cp], w[2kk][2cp+1], w[2kk+1][2cp+1])
__device__ __align__(16) float4 g_wp4[RR * (HC / 2) * (HC / 2)];
__device__ __align__(16) float g_wqk[RR * HC * 8];   // folded (W@q | W@k): [r][f][8]

// packed f32x2 FMA: d.lo += a.lo*b.lo ; d.hi += a.hi*b.hi
#define FMA2(d, a, b) asm("fma.rn.f32x2 %0, %1, %2, %0;" : "+l"(d) : "l"(a), "l"(b))

// ---------------- CSR build ----------------
__global__ void k_zero_deg() {
    int i = blockIdx.x * blockDim.x + threadIdx.x;
    if (i < NN) g_deg[i] = 0;
}

__global__ void k_hist(const int* __restrict__ ei) {
    int e = blockIdx.x * blockDim.x + threadIdx.x;
    if (e < EE) atomicAdd(&g_deg[ei[EE + e]], 1);
}

// single-block exclusive scan of g_deg -> g_rowstart / g_cursor
__global__ void k_scan() {
    __shared__ int sm[1024];
    __shared__ int s_carry;
    int tid = threadIdx.x;
    if (tid == 0) s_carry = 0;
    __syncthreads();
    const int TILES = (NN + 8191) / 8192;   // 7
    for (int tile = 0; tile < TILES; tile++) {
        int base = tile * 8192 + tid * 8;
        int v[8];
        int tsum = 0;
#pragma unroll
        for (int j = 0; j < 8; j++) {
            int idx = base + j;
            v[j] = (idx < NN) ? g_deg[idx] : 0;
            tsum += v[j];
        }
        sm[tid] = tsum;
        __syncthreads();
        for (int off = 1; off < 1024; off <<= 1) {
            int t = (tid >= off) ? sm[tid - off] : 0;
            __syncthreads();
            sm[tid] += t;
            __syncthreads();
        }
        int excl = s_carry + sm[tid] - tsum;
        int run = excl;
#pragma unroll
        for (int j = 0; j < 8; j++) {
            int idx = base + j;
            if (idx < NN) { g_rowstart[idx] = run; g_cursor[idx] = run; }
            run += v[j];
        }
        __syncthreads();
        if (tid == 0) s_carry += sm[1023];
        __syncthreads();
    }
    if (tid == 0) g_rowstart[NN] = s_carry;
}

__global__ void k_scatter(const int* __restrict__ ei, const int* __restrict__ etype) {
    int e = blockIdx.x * blockDim.x + threadIdx.x;
    if (e >= EE) return;
    int d = ei[EE + e];
    int s = ei[e];
    int t = etype[e];
    int pos = atomicAdd(&g_cursor[d], 1);
    g_csr[pos] = make_int2((t << 16) | s, e);
}

// ---------------- W pack: g_wp4[r][kk][cp] ----------------
__global__ void k_wp4(const float* __restrict__ w) {
    int idx = blockIdx.x * 256 + threadIdx.x;          // over RR*64*64 = 16384
    if (idx >= RR * 64 * 64) return;
    int r = idx >> 12;
    int rem = idx & 4095;
    int kk = rem >> 6, cp = rem & 63;
    const float* wr = w + ((size_t)r << 14);
    g_wp4[idx] = make_float4(wr[(2 * kk) * 128 + 2 * cp],
                             wr[(2 * kk + 1) * 128 + 2 * cp],
                             wr[(2 * kk) * 128 + 2 * cp + 1],
                             wr[(2 * kk + 1) * 128 + 2 * cp + 1]);
}

// ---------------- folded q/k: g_wqk[r][f][0:4]=W_r@q, [4:8]=W_r@k ----------------
__global__ void k_wqk(const float* __restrict__ w, const float* __restrict__ q,
                      const float* __restrict__ k) {
    int idx = blockIdx.x * 256 + threadIdx.x;    // 4096 total
    if (idx >= RR * HC * 8) return;
    int r = idx >> 10;
    int f = (idx >> 3) & 127;
    int o = idx & 7;
    const float* vec = (o < 4) ? q : k;
    int h = o & 3;
    const float* wrow = w + (r << 14) + (f << 7);
    float s = 0.f;
#pragma unroll 8
    for (int c = 0; c < HC; c++) s += wrow[c] * vec[c * 4 + h];
    g_wqk[idx] = s;
}

// ---------------- M = le @ e  (16x4, both layers) ----------------
__global__ void k_M(const float* __restrict__ le1, const float* __restrict__ e1,
                    const float* __restrict__ le3, const float* __restrict__ e3) {
    int t = threadIdx.x;
    if (t < 64) {
        int f = t >> 2, h = t & 3;
        float s = 0.f;
        for (int c = 0; c < HC; c++) s += le1[f * HC + c] * e1[c * HH + h];
        g_M1[t] = s;
    } else if (t < 128) {
        int u = t - 64;
        int f = u >> 2, h = u & 3;
        float s = 0.f;
        for (int c = 0; c < HC; c++) s += le3[f * HC + c] * e3[c * HH + h];
        g_M3[u] = s;
    }
}

// ---------------- batched GEMM via packed f32x2 FMA (vectorized loads) ----------------
// xw[r] = X @ W[r].  64-row x tile in smem (LDS.128 over K-pairs, broadcast);
// W via LDG.128 of col-paired K-pairs (coalesced, L1-resident).
__global__ void __launch_bounds__(256, 2) k_gemm2(const float* __restrict__ xin_arg, int layer) {
    __shared__ __align__(16) float xs[64 * 128];       // 32 KB
    const float* xin = (layer == 1) ? xin_arg : g_h;
    int r = blockIdx.y;
    int i0 = blockIdx.x * 64;
    int tid = threadIdx.x;
#pragma unroll
    for (int it = 0; it < 8; it++) {
        int q = tid + it * 256;          // float4 index within 64x128 tile
        int row = q >> 5, c4 = q & 31;
        float4 v = make_float4(0.f, 0.f, 0.f, 0.f);
        int gr = i0 + row;
        if (gr < NN) v = *(const float4*)(xin + (size_t)gr * 128 + c4 * 4);
        *(float4*)&xs[row * 128 + c4 * 4] = v;
    }
    __syncthreads();
    int ct = tid & 31, rt = tid >> 5;
    const ulonglong2* wp = (const ulonglong2*)g_wp4 + (size_t)r * 64 * 64;  // [kk][cp]
    const ulonglong2* xsp = (const ulonglong2*)xs;                          // [row][kk2]

    // acc[i][j][c2]: row i, col group j (cols 2ct / 64+2ct), sub-col c2, pair=even/odd K
    unsigned long long acc[8][2][2];
#pragma unroll
    for (int i = 0; i < 8; i++) {
        acc[i][0][0] = 0ULL; acc[i][0][1] = 0ULL;
        acc[i][1][0] = 0ULL; acc[i][1][1] = 0ULL;
    }

#pragma unroll 2
    for (int kk2 = 0; kk2 < 32; kk2++) {
        ulonglong2 wa0 = __ldg(&wp[(2 * kk2) * 64 + ct]);          // kk even: cols 2ct,2ct+1
        ulonglong2 wa1 = __ldg(&wp[(2 * kk2) * 64 + 32 + ct]);     // kk even: cols 64+2ct,65+2ct
        ulonglong2 wb0 = __ldg(&wp[(2 * kk2 + 1) * 64 + ct]);      // kk odd
        ulonglong2 wb1 = __ldg(&wp[(2 * kk2 + 1) * 64 + 32 + ct]);
#pragma unroll
        for (int i = 0; i < 8; i++) {
            ulonglong2 xv = xsp[(rt * 8 + i) * 32 + kk2];          // broadcast 16B: kk pair
            FMA2(acc[i][0][0], xv.x, wa0.x);
            FMA2(acc[i][0][1], xv.x, wa0.y);
            FMA2(acc[i][1][0], xv.x, wa1.x);
            FMA2(acc[i][1][1], xv.x, wa1.y);
            FMA2(acc[i][0][0], xv.y, wb0.x);
            FMA2(acc[i][0][1], xv.y, wb0.y);
            FMA2(acc[i][1][0], xv.y, wb1.x);
            FMA2(acc[i][1][1], xv.y, wb1.y);
        }
    }

    union U { unsigned long long u; float2 f; };
#pragma unroll
    for (int i = 0; i < 8; i++) {
        int gr = i0 + rt * 8 + i;
        if (gr < NN) {
            float* orow = &g_xw[((size_t)r * NN + gr) * 128];
            U a, b;
            a.u = acc[i][0][0]; b.u = acc[i][0][1];
            *(float2*)&orow[2 * ct] = make_float2(a.f.x + a.f.y, b.f.x + b.f.y);
            a.u = acc[i][1][0]; b.u = acc[i][1][1];
            *(float2*)&orow[64 + 2 * ct] = make_float2(a.f.x + a.f.y, b.f.x + b.f.y);
        }
    }
}

// ---------------- qn/kn = x @ g_wqk (node-parallel) ----------------
__global__ void k_qkx(const float* __restrict__ xin_arg, int layer) {
    __shared__ float xs2[32 * 129];          // padded, conflict-free across nodes
    __shared__ __align__(16) float sw[RR * HC * 8];
    const float* xin = (layer == 1) ? xin_arg : g_h;
    int tid = threadIdx.x;
    int n0 = blockIdx.x * 32;
#pragma unroll
    for (int it = 0; it < 4; it++) {
        int q = tid + it * 256;              // float4 index over 32x128
        int row = q >> 5, c4 = q & 31;
        float4 v = make_float4(0.f, 0.f, 0.f, 0.f);
        int gn = n0 + row;
        if (gn < NN) v = *(const float4*)(xin + (size_t)gn * 128 + c4 * 4);
        xs2[row * 129 + c4 * 4 + 0] = v.x;
        xs2[row * 129 + c4 * 4 + 1] = v.y;
        xs2[row * 129 + c4 * 4 + 2] = v.z;
        xs2[row * 129 + c4 * 4 + 3] = v.w;
    }
#pragma unroll
    for (int it = 0; it < 16; it++) sw[tid + it * 256] = g_wqk[tid + it * 256];
    __syncthreads();

    int nd = tid & 31;
    int slot = tid >> 5;                     // 0..7
    int r = slot >> 1;
    int half = slot & 1;                     // 0 = q heads, 1 = k heads
    int n = n0 + nd;
    if (n >= NN) return;

    float s0 = 0.f, s1 = 0.f, s2 = 0.f, s3 = 0.f;
#pragma unroll 8
    for (int k = 0; k < HC; k++) {
        float xv = xs2[nd * 129 + k];
        float4 wv = *(const float4*)&sw[(r * HC + k) * 8 + half * 4];
        s0 += xv * wv.x; s1 += xv * wv.y; s2 += xv * wv.z; s3 += xv * wv.w;
    }
    float* dst = (half == 0) ? g_qn : g_kn;
    *(float4*)&dst[((size_t)r * NN + n) * 4] = make_float4(s0, s1, s2, s3);
}

// ---------------- per-edge unnormalized attention probs (edge-parallel) ----------------
// p[e,h] = exp(leaky_relu(qn[t,dst,h] + kn[t,src,h] + (edge_attr[e] @ M)[h]))
__global__ void k_p(const int* __restrict__ ei, const int* __restrict__ etype,
                    const float* __restrict__ eattr, int layer) {
    __shared__ float sM[64];
    if (threadIdx.x < 64) sM[threadIdx.x] = (layer == 1) ? g_M1[threadIdx.x] : g_M3[threadIdx.x];
    __syncthreads();
    int e = blockIdx.x * 256 + threadIdx.x;
    if (e >= EE) return;
    int s = ei[e], d = ei[EE + e], t = etype[e];
    float4 qv = *(const float4*)&g_qn[((size_t)t * NN + d) * 4];
    float4 kv = *(const float4*)&g_kn[((size_t)t * NN + s) * 4];
    const float* a = eattr + (size_t)e * FE;
    float e0 = 0.f, e1 = 0.f, e2 = 0.f, e3 = 0.f;
#pragma unroll
    for (int f4 = 0; f4 < 4; f4++) {
        float4 av = *(const float4*)(a + f4 * 4);
        const float* m = &sM[f4 * 16];
        e0 += av.x * m[0] + av.y * m[4] + av.z * m[8]  + av.w * m[12];
        e1 += av.x * m[1] + av.y * m[5] + av.z * m[9]  + av.w * m[13];
        e2 += av.x * m[2] + av.y * m[6] + av.z * m[10] + av.w * m[14];
        e3 += av.x * m[3] + av.y * m[7] + av.z * m[11] + av.w * m[15];
    }
    float a0 = qv.x + kv.x + e0; a0 = a0 > 0.f ? a0 : 0.2f * a0;
    float a1 = qv.y + kv.y + e1; a1 = a1 > 0.f ? a1 : 0.2f * a1;
    float a2 = qv.z + kv.z + e2; a2 = a2 > 0.f ? a2 : 0.2f * a2;
    float a3 = qv.w + kv.w + e3; a3 = a3 > 0.f ? a3 : 0.2f * a3;
    g_p[e] = make_float4(__expf(a0), __expf(a1), __expf(a2), __expf(a3));
}

// ---------------- softmax-normalize + aggregate: warp per dst node ----------------
__global__ void k_agg(const float* __restrict__ bias, float* __restrict__ out, int layer) {
    int n = (blockIdx.x * blockDim.x + threadIdx.x) >> 5;
    int lane = threadIdx.x & 31;
    if (n >= NN) return;
    int rs = g_rowstart[n], re = g_rowstart[n + 1];

    float s0 = 0.f, s1 = 0.f, s2 = 0.f, s3 = 0.f;
    float acc0 = 0.f, acc1 = 0.f, acc2 = 0.f, acc3 = 0.f;
    int2 rec = (rs < re) ? g_csr[rs] : make_int2(0, 0);
    for (int e = rs; e < re; e++) {
        int2 cur = rec;
        if (e + 1 < re) rec = g_csr[e + 1];            // prefetch next record
        int et = cur.x >> 16, src = cur.x & 0xFFFF;
        float4 pv = g_p[cur.y];
        s0 += pv.x; s1 += pv.y; s2 += pv.z; s3 += pv.w;
        const float* xr = g_xw + ((size_t)et * NN + src) * 128 + lane;
        acc0 += pv.x * xr[0];
        acc1 += pv.y * xr[32];
        acc2 += pv.z * xr[64];
        acc3 += pv.w * xr[96];
    }

    const float EPS = 1e-16f;
    if (layer == 1) {
        float v0 = acc0 / (s0 + EPS) + bias[lane];
        float v1 = acc1 / (s1 + EPS) + bias[lane + 32];
        float v2 = acc2 / (s2 + EPS) + bias[lane + 64];
        float v3 = acc3 / (s3 + EPS) + bias[lane + 96];
        float* hp = g_h + (size_t)n * 128 + lane;
        hp[0]  = v0 > 0.f ? v0 : 0.f;
        hp[32] = v1 > 0.f ? v1 : 0.f;
        hp[64] = v2 > 0.f ? v2 : 0.f;
        hp[96] = v3 > 0.f ? v3 : 0.f;
    } else {
        float v = 0.25f * (acc0 / (s0 + EPS) + acc1 / (s1 + EPS) +
                           acc2 / (s2 + EPS) + acc3 / (s3 + EPS)) + bias[lane];
        out[(size_t)n * 32 + lane] = v;
    }
}

// ---------------- launch ----------------
extern "C" void kernel_launch(void* const* d_in, const int* in_sizes, int n_in,
                              void* d_out, int out_size) {
    const float* x     = (const float*)d_in[0];
    const int*   ei    = (const int*)  d_in[1];
    const float* eattr = (const float*)d_in[2];
    const int*   etype = (const int*)  d_in[3];
    const float* w1  = (const float*)d_in[4];
    const float* q1  = (const float*)d_in[5];
    const float* k1  = (const float*)d_in[6];
    const float* e1  = (const float*)d_in[7];
    const float* le1 = (const float*)d_in[8];
    const float* b1  = (const float*)d_in[9];
    const float* w3  = (const float*)d_in[10];
    const float* q3  = (const float*)d_in[11];
    const float* k3  = (const float*)d_in[12];
    const float* e3  = (const float*)d_in[13];
    const float* le3 = (const float*)d_in[14];
    const float* b3  = (const float*)d_in[15];
    float* out = (float*)d_out;

    const int EB = (EE + 255) / 256;         // 3125
    const int NB = (NN + 255) / 256;         // 196
    const int WP_B = (RR * 64 * 64 + 255) / 256;   // 64
    const int QKX_B = (NN + 31) / 32;        // 1563

    // ordered so the heavy GEMM lands at the launch index ncu samples
    k_zero_deg<<<NB, 256>>>();                             // 0
    k_hist<<<EB, 256>>>(ei);                               // 1
    k_wp4<<<WP_B, 256>>>(w1);                              // 2
    k_gemm2<<<dim3((NN + 63) / 64, RR), 256>>>(x, 1);      // 3  <- profile target
    k_scan<<<1, 1024>>>();                                 // 4
    k_scatter<<<EB, 256>>>(ei, etype);                     // 5
    k_M<<<1, 128>>>(le1, e1, le3, e3);                     // 6
    k_wqk<<<16, 256>>>(w1, q1, k1);                        // 7
    k_qkx<<<QKX_B, 256>>>(x, 1);                           // 8
    k_p<<<EB, 256>>>(ei, etype, eattr, 1);                 // 9
    k_agg<<<(NN + 7) / 8, 256>>>(b1, out, 1);              // 10

    k_wp4<<<WP_B, 256>>>(w3);                              // 11
    k_gemm2<<<dim3((NN + 63) / 64, RR), 256>>>(x, 2);      // 12
    k_wqk<<<16, 256>>>(w3, q3, k3);                        // 13
    k_qkx<<<QKX_B, 256>>>(x, 2);                           // 14
    k_p<<<EB, 256>>>(ei, etype, eattr, 2);                 // 15
    k_agg<<<(NN + 7) / 8, 256>>>(b3, out, 2);              // 16
}

// round 5
// speedup vs baseline: 2.1783x; 1.0955x over previous
#include <cuda_runtime.h>

// Problem constants
#define NN   50000
#define EE   800000
#define FE   16
#define RR   4
#define HH   4
#define CC   32
#define HC   128

// ---------------- scratch (static device globals; no allocation) ----------------
__device__ __align__(16) float g_xw[RR * NN * HC];   // per-relation projections (102.4MB)
__device__ __align__(16) float g_h[NN * HC];         // layer-1 output (relu)
__device__ __align__(16) float g_qn[RR * NN * HH];   // per-node query logits [r][n][4]
__device__ __align__(16) float g_kn[RR * NN * HH];   // per-node key logits   [r][n][4]
__device__ __align__(16) float4 g_pp[EE];            // per-edge probs, CSR-permuted
__device__ int   g_deg[NN];
__device__ int   g_rowstart[NN + 1];
__device__ int   g_cursor[NN];
__device__ int   g_csr32[EE];                        // (et<<16)|src, sorted by dst
__device__ int   g_pos[EE];                          // edge id -> csr position
__device__ float g_M1[FE * HH];
__device__ float g_M3[FE * HH];
// W col-pair+K-pair packed: g_wp4[r][kk][cp] = (w[2kk][2cp], w[2kk+1][2cp], w[2kk][2cp+1], w[2kk+1][2cp+1])
__device__ __align__(16) float4 g_wp4[RR * (HC / 2) * (HC / 2)];
__device__ __align__(16) float g_wqk[RR * HC * 8];   // folded (W@q | W@k): [r][f][8]

// packed f32x2 FMA: d.lo += a.lo*b.lo ; d.hi += a.hi*b.hi
#define FMA2(d, a, b) asm("fma.rn.f32x2 %0, %1, %2, %0;" : "+l"(d) : "l"(a), "l"(b))

// ---------------- CSR build ----------------
__global__ void k_zero_deg() {
    int i = blockIdx.x * blockDim.x + threadIdx.x;
    if (i < NN) g_deg[i] = 0;
}

__global__ void k_hist(const int* __restrict__ ei) {
    int e = blockIdx.x * blockDim.x + threadIdx.x;
    if (e < EE) atomicAdd(&g_deg[ei[EE + e]], 1);
}

// single-block exclusive scan of g_deg -> g_rowstart / g_cursor
__global__ void k_scan() {
    __shared__ int sm[1024];
    __shared__ int s_carry;
    int tid = threadIdx.x;
    if (tid == 0) s_carry = 0;
    __syncthreads();
    const int TILES = (NN + 8191) / 8192;   // 7
    for (int tile = 0; tile < TILES; tile++) {
        int base = tile * 8192 + tid * 8;
        int v[8];
        int tsum = 0;
#pragma unroll
        for (int j = 0; j < 8; j++) {
            int idx = base + j;
            v[j] = (idx < NN) ? g_deg[idx] : 0;
            tsum += v[j];
        }
        sm[tid] = tsum;
        __syncthreads();
        for (int off = 1; off < 1024; off <<= 1) {
            int t = (tid >= off) ? sm[tid - off] : 0;
            __syncthreads();
            sm[tid] += t;
            __syncthreads();
        }
        int excl = s_carry + sm[tid] - tsum;
        int run = excl;
#pragma unroll
        for (int j = 0; j < 8; j++) {
            int idx = base + j;
            if (idx < NN) { g_rowstart[idx] = run; g_cursor[idx] = run; }
            run += v[j];
        }
        __syncthreads();
        if (tid == 0) s_carry += sm[1023];
        __syncthreads();
    }
    if (tid == 0) g_rowstart[NN] = s_carry;
}

__global__ void k_scatter(const int* __restrict__ ei, const int* __restrict__ etype) {
    int e = blockIdx.x * blockDim.x + threadIdx.x;
    if (e >= EE) return;
    int d = ei[EE + e];
    int s = ei[e];
    int t = etype[e];
    int pos = atomicAdd(&g_cursor[d], 1);
    g_csr32[pos] = (t << 16) | s;
    g_pos[e] = pos;
}

// ---------------- W pack: g_wp4[r][kk][cp] ----------------
__global__ void k_wp4(const float* __restrict__ w) {
    int idx = blockIdx.x * 256 + threadIdx.x;          // over RR*64*64 = 16384
    if (idx >= RR * 64 * 64) return;
    int r = idx >> 12;
    int rem = idx & 4095;
    int kk = rem >> 6, cp = rem & 63;
    const float* wr = w + ((size_t)r << 14);
    g_wp4[idx] = make_float4(wr[(2 * kk) * 128 + 2 * cp],
                             wr[(2 * kk + 1) * 128 + 2 * cp],
                             wr[(2 * kk) * 128 + 2 * cp + 1],
                             wr[(2 * kk + 1) * 128 + 2 * cp + 1]);
}

// ---------------- folded q/k: g_wqk[r][f][0:4]=W_r@q, [4:8]=W_r@k ----------------
__global__ void k_wqk(const float* __restrict__ w, const float* __restrict__ q,
                      const float* __restrict__ k) {
    int idx = blockIdx.x * 256 + threadIdx.x;    // 4096 total
    if (idx >= RR * HC * 8) return;
    int r = idx >> 10;
    int f = (idx >> 3) & 127;
    int o = idx & 7;
    const float* vec = (o < 4) ? q : k;
    int h = o & 3;
    const float* wrow = w + (r << 14) + (f << 7);
    float s = 0.f;
#pragma unroll 8
    for (int c = 0; c < HC; c++) s += wrow[c] * vec[c * 4 + h];
    g_wqk[idx] = s;
}

// ---------------- M = le @ e  (16x4, both layers) ----------------
__global__ void k_M(const float* __restrict__ le1, const float* __restrict__ e1,
                    const float* __restrict__ le3, const float* __restrict__ e3) {
    int t = threadIdx.x;
    if (t < 64) {
        int f = t >> 2, h = t & 3;
        float s = 0.f;
        for (int c = 0; c < HC; c++) s += le1[f * HC + c] * e1[c * HH + h];
        g_M1[t] = s;
    } else if (t < 128) {
        int u = t - 64;
        int f = u >> 2, h = u & 3;
        float s = 0.f;
        for (int c = 0; c < HC; c++) s += le3[f * HC + c] * e3[c * HH + h];
        g_M3[u] = s;
    }
}

// ---------------- batched GEMM via packed f32x2 FMA ----------------
__global__ void __launch_bounds__(256, 2) k_gemm2(const float* __restrict__ xin_arg, int layer) {
    __shared__ __align__(16) float xs[64 * 128];       // 32 KB
    const float* xin = (layer == 1) ? xin_arg : g_h;
    int r = blockIdx.y;
    int i0 = blockIdx.x * 64;
    int tid = threadIdx.x;
#pragma unroll
    for (int it = 0; it < 8; it++) {
        int q = tid + it * 256;          // float4 index within 64x128 tile
        int row = q >> 5, c4 = q & 31;
        float4 v = make_float4(0.f, 0.f, 0.f, 0.f);
        int gr = i0 + row;
        if (gr < NN) v = *(const float4*)(xin + (size_t)gr * 128 + c4 * 4);
        *(float4*)&xs[row * 128 + c4 * 4] = v;
    }
    __syncthreads();
    int ct = tid & 31, rt = tid >> 5;
    const ulonglong2* wp = (const ulonglong2*)g_wp4 + (size_t)r * 64 * 64;  // [kk][cp]
    const ulonglong2* xsp = (const ulonglong2*)xs;                          // [row][kk2]

    unsigned long long acc[8][2][2];
#pragma unroll
    for (int i = 0; i < 8; i++) {
        acc[i][0][0] = 0ULL; acc[i][0][1] = 0ULL;
        acc[i][1][0] = 0ULL; acc[i][1][1] = 0ULL;
    }

#pragma unroll 2
    for (int kk2 = 0; kk2 < 32; kk2++) {
        ulonglong2 wa0 = __ldg(&wp[(2 * kk2) * 64 + ct]);
        ulonglong2 wa1 = __ldg(&wp[(2 * kk2) * 64 + 32 + ct]);
        ulonglong2 wb0 = __ldg(&wp[(2 * kk2 + 1) * 64 + ct]);
        ulonglong2 wb1 = __ldg(&wp[(2 * kk2 + 1) * 64 + 32 + ct]);
#pragma unroll
        for (int i = 0; i < 8; i++) {
            ulonglong2 xv = xsp[(rt * 8 + i) * 32 + kk2];          // broadcast 16B
            FMA2(acc[i][0][0], xv.x, wa0.x);
            FMA2(acc[i][0][1], xv.x, wa0.y);
            FMA2(acc[i][1][0], xv.x, wa1.x);
            FMA2(acc[i][1][1], xv.x, wa1.y);
            FMA2(acc[i][0][0], xv.y, wb0.x);
            FMA2(acc[i][0][1], xv.y, wb0.y);
            FMA2(acc[i][1][0], xv.y, wb1.x);
            FMA2(acc[i][1][1], xv.y, wb1.y);
        }
    }

    union U { unsigned long long u; float2 f; };
#pragma unroll
    for (int i = 0; i < 8; i++) {
        int gr = i0 + rt * 8 + i;
        if (gr < NN) {
            float* orow = &g_xw[((size_t)r * NN + gr) * 128];
            U a, b;
            a.u = acc[i][0][0]; b.u = acc[i][0][1];
            *(float2*)&orow[2 * ct] = make_float2(a.f.x + a.f.y, b.f.x + b.f.y);
            a.u = acc[i][1][0]; b.u = acc[i][1][1];
            *(float2*)&orow[64 + 2 * ct] = make_float2(a.f.x + a.f.y, b.f.x + b.f.y);
        }
    }
}

// ---------------- qn/kn = x @ g_wqk (node-parallel) ----------------
__global__ void k_qkx(const float* __restrict__ xin_arg, int layer) {
    __shared__ float xs2[32 * 129];
    __shared__ __align__(16) float sw[RR * HC * 8];
    const float* xin = (layer == 1) ? xin_arg : g_h;
    int tid = threadIdx.x;
    int n0 = blockIdx.x * 32;
#pragma unroll
    for (int it = 0; it < 4; it++) {
        int q = tid + it * 256;
        int row = q >> 5, c4 = q & 31;
        float4 v = make_float4(0.f, 0.f, 0.f, 0.f);
        int gn = n0 + row;
        if (gn < NN) v = *(const float4*)(xin + (size_t)gn * 128 + c4 * 4);
        xs2[row * 129 + c4 * 4 + 0] = v.x;
        xs2[row * 129 + c4 * 4 + 1] = v.y;
        xs2[row * 129 + c4 * 4 + 2] = v.z;
        xs2[row * 129 + c4 * 4 + 3] = v.w;
    }
#pragma unroll
    for (int it = 0; it < 16; it++) sw[tid + it * 256] = g_wqk[tid + it * 256];
    __syncthreads();

    int nd = tid & 31;
    int slot = tid >> 5;
    int r = slot >> 1;
    int half = slot & 1;
    int n = n0 + nd;
    if (n >= NN) return;

    float s0 = 0.f, s1 = 0.f, s2 = 0.f, s3 = 0.f;
#pragma unroll 8
    for (int k = 0; k < HC; k++) {
        float xv = xs2[nd * 129 + k];
        float4 wv = *(const float4*)&sw[(r * HC + k) * 8 + half * 4];
        s0 += xv * wv.x; s1 += xv * wv.y; s2 += xv * wv.z; s3 += xv * wv.w;
    }
    float* dst = (half == 0) ? g_qn : g_kn;
    *(float4*)&dst[((size_t)r * NN + n) * 4] = make_float4(s0, s1, s2, s3);
}

// ---------------- per-edge probs, written in CSR order ----------------
// g_pp[pos(e)] = exp(leaky_relu(qn[t,dst] + kn[t,src] + edge_attr[e] @ M))
__global__ void k_p(const int* __restrict__ ei, const int* __restrict__ etype,
                    const float* __restrict__ eattr, int layer) {
    __shared__ float sM[64];
    if (threadIdx.x < 64) sM[threadIdx.x] = (layer == 1) ? g_M1[threadIdx.x] : g_M3[threadIdx.x];
    __syncthreads();
    int e = blockIdx.x * 256 + threadIdx.x;
    if (e >= EE) return;
    int s = ei[e], d = ei[EE + e], t = etype[e];
    float4 qv = *(const float4*)&g_qn[((size_t)t * NN + d) * 4];
    float4 kv = *(const float4*)&g_kn[((size_t)t * NN + s) * 4];
    const float* a = eattr + (size_t)e * FE;
    float e0 = 0.f, e1 = 0.f, e2 = 0.f, e3 = 0.f;
#pragma unroll
    for (int f4 = 0; f4 < 4; f4++) {
        float4 av = *(const float4*)(a + f4 * 4);
        const float* m = &sM[f4 * 16];
        e0 += av.x * m[0] + av.y * m[4] + av.z * m[8]  + av.w * m[12];
        e1 += av.x * m[1] + av.y * m[5] + av.z * m[9]  + av.w * m[13];
        e2 += av.x * m[2] + av.y * m[6] + av.z * m[10] + av.w * m[14];
        e3 += av.x * m[3] + av.y * m[7] + av.z * m[11] + av.w * m[15];
    }
    float a0 = qv.x + kv.x + e0; a0 = a0 > 0.f ? a0 : 0.2f * a0;
    float a1 = qv.y + kv.y + e1; a1 = a1 > 0.f ? a1 : 0.2f * a1;
    float a2 = qv.z + kv.z + e2; a2 = a2 > 0.f ? a2 : 0.2f * a2;
    float a3 = qv.w + kv.w + e3; a3 = a3 > 0.f ? a3 : 0.2f * a3;
    g_pp[g_pos[e]] = make_float4(__expf(a0), __expf(a1), __expf(a2), __expf(a3));
}

// ---------------- softmax-normalize + aggregate: warp per dst node ----------------
// CSR records + probs are streamed (warp-uniform); only xw rows are gathered.
// 4x unrolled with front-batched loads to raise MLP.
__global__ void k_agg(const float* __restrict__ bias, float* __restrict__ out, int layer) {
    int n = (blockIdx.x * blockDim.x + threadIdx.x) >> 5;
    int lane = threadIdx.x & 31;
    if (n >= NN) return;
    int rs = g_rowstart[n], re = g_rowstart[n + 1];

    float s0 = 0.f, s1 = 0.f, s2 = 0.f, s3 = 0.f;
    float acc0 = 0.f, acc1 = 0.f, acc2 = 0.f, acc3 = 0.f;

    int e = rs;
    for (; e + 4 <= re; e += 4) {
        int r0 = g_csr32[e], r1 = g_csr32[e + 1], r2 = g_csr32[e + 2], r3 = g_csr32[e + 3];
        float4 p0 = g_pp[e], p1 = g_pp[e + 1], p2 = g_pp[e + 2], p3 = g_pp[e + 3];
        const float* x0 = g_xw + ((size_t)(r0 >> 16) * NN + (r0 & 0xFFFF)) * 128 + lane;
        const float* x1 = g_xw + ((size_t)(r1 >> 16) * NN + (r1 & 0xFFFF)) * 128 + lane;
        const float* x2 = g_xw + ((size_t)(r2 >> 16) * NN + (r2 & 0xFFFF)) * 128 + lane;
        const float* x3 = g_xw + ((size_t)(r3 >> 16) * NN + (r3 & 0xFFFF)) * 128 + lane;
        // front-batch all 16 gathers
        float v00 = x0[0], v01 = x0[32], v02 = x0[64], v03 = x0[96];
        float v10 = x1[0], v11 = x1[32], v12 = x1[64], v13 = x1[96];
        float v20 = x2[0], v21 = x2[32], v22 = x2[64], v23 = x2[96];
        float v30 = x3[0], v31 = x3[32], v32 = x3[64], v33 = x3[96];
        s0 += (p0.x + p1.x) + (p2.x + p3.x);
        s1 += (p0.y + p1.y) + (p2.y + p3.y);
        s2 += (p0.z + p1.z) + (p2.z + p3.z);
        s3 += (p0.w + p1.w) + (p2.w + p3.w);
        acc0 += p0.x * v00 + p1.x * v10 + p2.x * v20 + p3.x * v30;
        acc1 += p0.y * v01 + p1.y * v11 + p2.y * v21 + p3.y * v31;
        acc2 += p0.z * v02 + p1.z * v12 + p2.z * v22 + p3.z * v32;
        acc3 += p0.w * v03 + p1.w * v13 + p2.w * v23 + p3.w * v33;
    }
    for (; e < re; e++) {
        int r0 = g_csr32[e];
        float4 p0 = g_pp[e];
        const float* x0 = g_xw + ((size_t)(r0 >> 16) * NN + (r0 & 0xFFFF)) * 128 + lane;
        s0 += p0.x; s1 += p0.y; s2 += p0.z; s3 += p0.w;
        acc0 += p0.x * x0[0];
        acc1 += p0.y * x0[32];
        acc2 += p0.z * x0[64];
        acc3 += p0.w * x0[96];
    }

    const float EPS = 1e-16f;
    if (layer == 1) {
        float v0 = acc0 / (s0 + EPS) + bias[lane];
        float v1 = acc1 / (s1 + EPS) + bias[lane + 32];
        float v2 = acc2 / (s2 + EPS) + bias[lane + 64];
        float v3 = acc3 / (s3 + EPS) + bias[lane + 96];
        float* hp = g_h + (size_t)n * 128 + lane;
        hp[0]  = v0 > 0.f ? v0 : 0.f;
        hp[32] = v1 > 0.f ? v1 : 0.f;
        hp[64] = v2 > 0.f ? v2 : 0.f;
        hp[96] = v3 > 0.f ? v3 : 0.f;
    } else {
        float v = 0.25f * (acc0 / (s0 + EPS) + acc1 / (s1 + EPS) +
                           acc2 / (s2 + EPS) + acc3 / (s3 + EPS)) + bias[lane];
        out[(size_t)n * 32 + lane] = v;
    }
}

// ---------------- launch ----------------
extern "C" void kernel_launch(void* const* d_in, const int* in_sizes, int n_in,
                              void* d_out, int out_size) {
    const float* x     = (const float*)d_in[0];
    const int*   ei    = (const int*)  d_in[1];
    const float* eattr = (const float*)d_in[2];
    const int*   etype = (const int*)  d_in[3];
    const float* w1  = (const float*)d_in[4];
    const float* q1  = (const float*)d_in[5];
    const float* k1  = (const float*)d_in[6];
    const float* e1  = (const float*)d_in[7];
    const float* le1 = (const float*)d_in[8];
    const float* b1  = (const float*)d_in[9];
    const float* w3  = (const float*)d_in[10];
    const float* q3  = (const float*)d_in[11];
    const float* k3  = (const float*)d_in[12];
    const float* e3  = (const float*)d_in[13];
    const float* le3 = (const float*)d_in[14];
    const float* b3  = (const float*)d_in[15];
    float* out = (float*)d_out;

    const int EB = (EE + 255) / 256;         // 3125
    const int NB = (NN + 255) / 256;         // 196
    const int WP_B = (RR * 64 * 64 + 255) / 256;   // 64
    const int QKX_B = (NN + 31) / 32;        // 1563

    k_zero_deg<<<NB, 256>>>();                             // 0
    k_hist<<<EB, 256>>>(ei);                               // 1
    k_wp4<<<WP_B, 256>>>(w1);                              // 2
    k_gemm2<<<dim3((NN + 63) / 64, RR), 256>>>(x, 1);      // 3  <- profile target
    k_scan<<<1, 1024>>>();                                 // 4
    k_scatter<<<EB, 256>>>(ei, etype);                     // 5
    k_M<<<1, 128>>>(le1, e1, le3, e3);                     // 6
    k_wqk<<<16, 256>>>(w1, q1, k1);                        // 7
    k_qkx<<<QKX_B, 256>>>(x, 1);                           // 8
    k_p<<<EB, 256>>>(ei, etype, eattr, 1);                 // 9
    k_agg<<<(NN + 7) / 8, 256>>>(b1, out, 1);              // 10

    k_wp4<<<WP_B, 256>>>(w3);                              // 11
    k_gemm2<<<dim3((NN + 63) / 64, RR), 256>>>(x, 2);      // 12
    k_wqk<<<16, 256>>>(w3, q3, k3);                        // 13
    k_qkx<<<QKX_B, 256>>>(x, 2);                           // 14
    k_p<<<EB, 256>>>(ei, etype, eattr, 2);                 // 15
    k_agg<<<(NN + 7) / 8, 256>>>(b3, out, 2);              // 16
}

// round 6
// speedup vs baseline: 2.9262x; 1.3433x over previous
#include <cuda_runtime.h>
#include <cstdint>

// Problem constants
#define NN   50000
#define EE   800000
#define FE   16
#define RR   4
#define HH   4
#define CC   32
#define HC   128

// ---------------- scratch (static device globals; no allocation) ----------------
__device__ __align__(16) float g_xw[RR * NN * HC];   // per-relation projections (102.4MB)
__device__ __align__(16) float g_h[NN * HC];         // layer-1 output (relu)
__device__ __align__(16) float g_qn[RR * NN * HH];   // per-node query logits [r][n][4]
__device__ __align__(16) float g_kn[RR * NN * HH];   // per-node key logits   [r][n][4]
__device__ __align__(16) float4 g_pp[EE];            // per-edge probs, CSR-permuted
__device__ int   g_deg[NN];
__device__ int   g_rowstart[NN + 1];
__device__ int   g_cursor[NN];
__device__ int   g_csr32[EE];                        // (et<<16)|src, sorted by dst
__device__ int   g_pos[EE];                          // edge id -> csr position
__device__ float g_M1[FE * HH];
__device__ float g_M3[FE * HH];
// W pre-fragmented for mma.m16n8k8 tf32: [r][phase p(4)][s(4)][ntile j(16)][lane(32)][2]
__device__ __align__(16) uint32_t g_wf[RR * 4 * 4 * 16 * 32 * 2];
__device__ __align__(16) float g_wqk[RR * HC * 8];   // folded (W@q | W@k): [r][f][8]

__device__ __forceinline__ uint32_t f2tf32(float f) {
    uint32_t u;
    asm("cvt.rna.tf32.f32 %0, %1;" : "=r"(u) : "f"(f));
    return u;
}

// ---------------- CSR build ----------------
__global__ void k_zero_deg() {
    int i = blockIdx.x * blockDim.x + threadIdx.x;
    if (i < NN) g_deg[i] = 0;
}

__global__ void k_hist(const int* __restrict__ ei) {
    int e = blockIdx.x * blockDim.x + threadIdx.x;
    if (e < EE) atomicAdd(&g_deg[ei[EE + e]], 1);
}

// single-block exclusive scan of g_deg -> g_rowstart / g_cursor
__global__ void k_scan() {
    __shared__ int sm[1024];
    __shared__ int s_carry;
    int tid = threadIdx.x;
    if (tid == 0) s_carry = 0;
    __syncthreads();
    const int TILES = (NN + 8191) / 8192;   // 7
    for (int tile = 0; tile < TILES; tile++) {
        int base = tile * 8192 + tid * 8;
        int v[8];
        int tsum = 0;
#pragma unroll
        for (int j = 0; j < 8; j++) {
            int idx = base + j;
            v[j] = (idx < NN) ? g_deg[idx] : 0;
            tsum += v[j];
        }
        sm[tid] = tsum;
        __syncthreads();
        for (int off = 1; off < 1024; off <<= 1) {
            int t = (tid >= off) ? sm[tid - off] : 0;
            __syncthreads();
            sm[tid] += t;
            __syncthreads();
        }
        int excl = s_carry + sm[tid] - tsum;
        int run = excl;
#pragma unroll
        for (int j = 0; j < 8; j++) {
            int idx = base + j;
            if (idx < NN) { g_rowstart[idx] = run; g_cursor[idx] = run; }
            run += v[j];
        }
        __syncthreads();
        if (tid == 0) s_carry += sm[1023];
        __syncthreads();
    }
    if (tid == 0) g_rowstart[NN] = s_carry;
}

__global__ void k_scatter(const int* __restrict__ ei, const int* __restrict__ etype) {
    int e = blockIdx.x * blockDim.x + threadIdx.x;
    if (e >= EE) return;
    int d = ei[EE + e];
    int s = ei[e];
    int t = etype[e];
    int pos = atomicAdd(&g_cursor[d], 1);
    g_csr32[pos] = (t << 16) | s;
    g_pos[e] = pos;
}

// ---------------- W fragment pack for mma.m16n8k8 tf32 ----------------
// b0 = W[k = p*32 + s*8 + lane%4][c = j*8 + lane/4] ; b1 = same with k+4
__global__ void k_wfrag(const float* __restrict__ w) {
    int idx = blockIdx.x * 256 + threadIdx.x;          // over 65536
    if (idx >= RR * 4 * 4 * 16 * 32 * 2) return;
    int b    = idx & 1;
    int lane = (idx >> 1) & 31;
    int j    = (idx >> 6) & 15;
    int s    = (idx >> 10) & 3;
    int p    = (idx >> 12) & 3;
    int r    = idx >> 14;
    int k = p * 32 + s * 8 + (b ? 4 : 0) + (lane & 3);
    int c = j * 8 + (lane >> 2);
    g_wf[idx] = f2tf32(w[((size_t)r << 14) + k * 128 + c]);
}

// ---------------- folded q/k: g_wqk[r][f][0:4]=W_r@q, [4:8]=W_r@k ----------------
__global__ void k_wqk(const float* __restrict__ w, const float* __restrict__ q,
                      const float* __restrict__ k) {
    int idx = blockIdx.x * 256 + threadIdx.x;    // 4096 total
    if (idx >= RR * HC * 8) return;
    int r = idx >> 10;
    int f = (idx >> 3) & 127;
    int o = idx & 7;
    const float* vec = (o < 4) ? q : k;
    int h = o & 3;
    const float* wrow = w + (r << 14) + (f << 7);
    float s = 0.f;
#pragma unroll 8
    for (int c = 0; c < HC; c++) s += wrow[c] * vec[c * 4 + h];
    g_wqk[idx] = s;
}

// ---------------- M = le @ e  (16x4, both layers) ----------------
__global__ void k_M(const float* __restrict__ le1, const float* __restrict__ e1,
                    const float* __restrict__ le3, const float* __restrict__ e3) {
    int t = threadIdx.x;
    if (t < 64) {
        int f = t >> 2, h = t & 3;
        float s = 0.f;
        for (int c = 0; c < HC; c++) s += le1[f * HC + c] * e1[c * HH + h];
        g_M1[t] = s;
    } else if (t < 128) {
        int u = t - 64;
        int f = u >> 2, h = u & 3;
        float s = 0.f;
        for (int c = 0; c < HC; c++) s += le3[f * HC + c] * e3[c * HH + h];
        g_M3[u] = s;
    }
}

// ---------------- tensor-core GEMM: xw[r] = X @ W[r] (tf32 mma, fp32 accum) ----------------
// Block: 256 thr / 8 warps. Tile M=128 (16 rows/warp), N=128, K in 4 phases of 32.
// xs stride 36 -> A-fragment LDS bank-exact; W pre-fragmented -> conflict-free LDS.64.
#define XS_STRIDE 36
__global__ void __launch_bounds__(256) k_gemmt(const float* __restrict__ xin_arg, int layer) {
    __shared__ uint32_t xs[128 * XS_STRIDE];           // 18.4 KB (tf32 bits)
    __shared__ uint32_t ws[4 * 16 * 32 * 2];           // 16 KB per K-phase
    const float* xin = (layer == 1) ? xin_arg : g_h;
    int r = blockIdx.y;
    int i0 = blockIdx.x * 128;
    int tid = threadIdx.x;
    int lane = tid & 31, wid = tid >> 5;
    int wr = wid * 16;                                  // warp row offset

    float d[16][4];
#pragma unroll
    for (int j = 0; j < 16; j++) {
        d[j][0] = 0.f; d[j][1] = 0.f; d[j][2] = 0.f; d[j][3] = 0.f;
    }

    const uint32_t* wsrc = g_wf + (size_t)r * 16384;

    for (int p = 0; p < 4; p++) {
        __syncthreads();                                // protect prev phase reads
        // load x[:, p*32 .. p*32+32) : 128 rows x 32 cols = 1024 float4
#pragma unroll
        for (int it = 0; it < 4; it++) {
            int q = tid + it * 256;                     // float4 index
            int row = q >> 3, c4 = q & 7;
            float4 v = make_float4(0.f, 0.f, 0.f, 0.f);
            int gr = i0 + row;
            if (gr < NN) v = *(const float4*)(xin + (size_t)gr * 128 + p * 32 + c4 * 4);
            uint32_t* dst = &xs[row * XS_STRIDE + c4 * 4];
            dst[0] = f2tf32(v.x); dst[1] = f2tf32(v.y);
            dst[2] = f2tf32(v.z); dst[3] = f2tf32(v.w);
        }
        // load W fragments for this phase: 4096 uints = 1024 uint4
        const uint4* wsp = (const uint4*)(wsrc + p * 4096);
#pragma unroll
        for (int it = 0; it < 4; it++) {
            int q = tid + it * 256;
            ((uint4*)ws)[q] = __ldg(&wsp[q]);
        }
        __syncthreads();

#pragma unroll
        for (int s = 0; s < 4; s++) {
            int arow = wr + (lane >> 2);
            int acol = s * 8 + (lane & 3);
            uint32_t a0 = xs[arow * XS_STRIDE + acol];
            uint32_t a1 = xs[(arow + 8) * XS_STRIDE + acol];
            uint32_t a2 = xs[arow * XS_STRIDE + acol + 4];
            uint32_t a3 = xs[(arow + 8) * XS_STRIDE + acol + 4];
            const uint32_t* wrow = &ws[(s * 16) * 64];
#pragma unroll
            for (int j = 0; j < 16; j++) {
                uint2 bv = *(const uint2*)&wrow[j * 64 + lane * 2];
                asm volatile(
                    "mma.sync.aligned.m16n8k8.row.col.f32.tf32.tf32.f32 "
                    "{%0,%1,%2,%3}, {%4,%5,%6,%7}, {%8,%9}, {%0,%1,%2,%3};"
                    : "+f"(d[j][0]), "+f"(d[j][1]), "+f"(d[j][2]), "+f"(d[j][3])
                    : "r"(a0), "r"(a1), "r"(a2), "r"(a3), "r"(bv.x), "r"(bv.y));
            }
        }
    }

    // epilogue: c0/c1 -> (row, col..col+1), c2/c3 -> (row+8, ...)
    int row0 = i0 + wr + (lane >> 2);
    int row1 = row0 + 8;
    float* base = g_xw + (size_t)r * NN * HC;
#pragma unroll
    for (int j = 0; j < 16; j++) {
        int col = j * 8 + (lane & 3) * 2;
        if (row0 < NN) *(float2*)&base[(size_t)row0 * 128 + col] = make_float2(d[j][0], d[j][1]);
        if (row1 < NN) *(float2*)&base[(size_t)row1 * 128 + col] = make_float2(d[j][2], d[j][3]);
    }
}

// ---------------- qn/kn = x @ g_wqk (node-parallel, full fp32) ----------------
__global__ void k_qkx(const float* __restrict__ xin_arg, int layer) {
    __shared__ float xs2[32 * 129];
    __shared__ __align__(16) float sw[RR * HC * 8];
    const float* xin = (layer == 1) ? xin_arg : g_h;
    int tid = threadIdx.x;
    int n0 = blockIdx.x * 32;
#pragma unroll
    for (int it = 0; it < 4; it++) {
        int q = tid + it * 256;
        int row = q >> 5, c4 = q & 31;
        float4 v = make_float4(0.f, 0.f, 0.f, 0.f);
        int gn = n0 + row;
        if (gn < NN) v = *(const float4*)(xin + (size_t)gn * 128 + c4 * 4);
        xs2[row * 129 + c4 * 4 + 0] = v.x;
        xs2[row * 129 + c4 * 4 + 1] = v.y;
        xs2[row * 129 + c4 * 4 + 2] = v.z;
        xs2[row * 129 + c4 * 4 + 3] = v.w;
    }
#pragma unroll
    for (int it = 0; it < 16; it++) sw[tid + it * 256] = g_wqk[tid + it * 256];
    __syncthreads();

    int nd = tid & 31;
    int slot = tid >> 5;
    int r = slot >> 1;
    int half = slot & 1;
    int n = n0 + nd;
    if (n >= NN) return;

    float s0 = 0.f, s1 = 0.f, s2 = 0.f, s3 = 0.f;
#pragma unroll 8
    for (int k = 0; k < HC; k++) {
        float xv = xs2[nd * 129 + k];
        float4 wv = *(const float4*)&sw[(r * HC + k) * 8 + half * 4];
        s0 += xv * wv.x; s1 += xv * wv.y; s2 += xv * wv.z; s3 += xv * wv.w;
    }
    float* dst = (half == 0) ? g_qn : g_kn;
    *(float4*)&dst[((size_t)r * NN + n) * 4] = make_float4(s0, s1, s2, s3);
}

// ---------------- per-edge probs, written in CSR order ----------------
__global__ void k_p(const int* __restrict__ ei, const int* __restrict__ etype,
                    const float* __restrict__ eattr, int layer) {
    __shared__ float sM[64];
    if (threadIdx.x < 64) sM[threadIdx.x] = (layer == 1) ? g_M1[threadIdx.x] : g_M3[threadIdx.x];
    __syncthreads();
    int e = blockIdx.x * 256 + threadIdx.x;
    if (e >= EE) return;
    int s = ei[e], d = ei[EE + e], t = etype[e];
    float4 qv = *(const float4*)&g_qn[((size_t)t * NN + d) * 4];
    float4 kv = *(const float4*)&g_kn[((size_t)t * NN + s) * 4];
    const float* a = eattr + (size_t)e * FE;
    float e0 = 0.f, e1 = 0.f, e2 = 0.f, e3 = 0.f;
#pragma unroll
    for (int f4 = 0; f4 < 4; f4++) {
        float4 av = *(const float4*)(a + f4 * 4);
        const float* m = &sM[f4 * 16];
        e0 += av.x * m[0] + av.y * m[4] + av.z * m[8]  + av.w * m[12];
        e1 += av.x * m[1] + av.y * m[5] + av.z * m[9]  + av.w * m[13];
        e2 += av.x * m[2] + av.y * m[6] + av.z * m[10] + av.w * m[14];
        e3 += av.x * m[3] + av.y * m[7] + av.z * m[11] + av.w * m[15];
    }
    float a0 = qv.x + kv.x + e0; a0 = a0 > 0.f ? a0 : 0.2f * a0;
    float a1 = qv.y + kv.y + e1; a1 = a1 > 0.f ? a1 : 0.2f * a1;
    float a2 = qv.z + kv.z + e2; a2 = a2 > 0.f ? a2 : 0.2f * a2;
    float a3 = qv.w + kv.w + e3; a3 = a3 > 0.f ? a3 : 0.2f * a3;
    g_pp[g_pos[e]] = make_float4(__expf(a0), __expf(a1), __expf(a2), __expf(a3));
}

// ---------------- softmax-normalize + aggregate: warp per dst node ----------------
__global__ void k_agg(const float* __restrict__ bias, float* __restrict__ out, int layer) {
    int n = (blockIdx.x * blockDim.x + threadIdx.x) >> 5;
    int lane = threadIdx.x & 31;
    if (n >= NN) return;
    int rs = g_rowstart[n], re = g_rowstart[n + 1];

    float s0 = 0.f, s1 = 0.f, s2 = 0.f, s3 = 0.f;
    float acc0 = 0.f, acc1 = 0.f, acc2 = 0.f, acc3 = 0.f;

    int e = rs;
    for (; e + 4 <= re; e += 4) {
        int r0 = g_csr32[e], r1 = g_csr32[e + 1], r2 = g_csr32[e + 2], r3 = g_csr32[e + 3];
        float4 p0 = g_pp[e], p1 = g_pp[e + 1], p2 = g_pp[e + 2], p3 = g_pp[e + 3];
        const float* x0 = g_xw + ((size_t)(r0 >> 16) * NN + (r0 & 0xFFFF)) * 128 + lane;
        const float* x1 = g_xw + ((size_t)(r1 >> 16) * NN + (r1 & 0xFFFF)) * 128 + lane;
        const float* x2 = g_xw + ((size_t)(r2 >> 16) * NN + (r2 & 0xFFFF)) * 128 + lane;
        const float* x3 = g_xw + ((size_t)(r3 >> 16) * NN + (r3 & 0xFFFF)) * 128 + lane;
        float v00 = x0[0], v01 = x0[32], v02 = x0[64], v03 = x0[96];
        float v10 = x1[0], v11 = x1[32], v12 = x1[64], v13 = x1[96];
        float v20 = x2[0], v21 = x2[32], v22 = x2[64], v23 = x2[96];
        float v30 = x3[0], v31 = x3[32], v32 = x3[64], v33 = x3[96];
        s0 += (p0.x + p1.x) + (p2.x + p3.x);
        s1 += (p0.y + p1.y) + (p2.y + p3.y);
        s2 += (p0.z + p1.z) + (p2.z + p3.z);
        s3 += (p0.w + p1.w) + (p2.w + p3.w);
        acc0 += p0.x * v00 + p1.x * v10 + p2.x * v20 + p3.x * v30;
        acc1 += p0.y * v01 + p1.y * v11 + p2.y * v21 + p3.y * v31;
        acc2 += p0.z * v02 + p1.z * v12 + p2.z * v22 + p3.z * v32;
        acc3 += p0.w * v03 + p1.w * v13 + p2.w * v23 + p3.w * v33;
    }
    for (; e < re; e++) {
        int r0 = g_csr32[e];
        float4 p0 = g_pp[e];
        const float* x0 = g_xw + ((size_t)(r0 >> 16) * NN + (r0 & 0xFFFF)) * 128 + lane;
        s0 += p0.x; s1 += p0.y; s2 += p0.z; s3 += p0.w;
        acc0 += p0.x * x0[0];
        acc1 += p0.y * x0[32];
        acc2 += p0.z * x0[64];
        acc3 += p0.w * x0[96];
    }

    const float EPS = 1e-16f;
    if (layer == 1) {
        float v0 = acc0 / (s0 + EPS) + bias[lane];
        float v1 = acc1 / (s1 + EPS) + bias[lane + 32];
        float v2 = acc2 / (s2 + EPS) + bias[lane + 64];
        float v3 = acc3 / (s3 + EPS) + bias[lane + 96];
        float* hp = g_h + (size_t)n * 128 + lane;
        hp[0]  = v0 > 0.f ? v0 : 0.f;
        hp[32] = v1 > 0.f ? v1 : 0.f;
        hp[64] = v2 > 0.f ? v2 : 0.f;
        hp[96] = v3 > 0.f ? v3 : 0.f;
    } else {
        float v = 0.25f * (acc0 / (s0 + EPS) + acc1 / (s1 + EPS) +
                           acc2 / (s2 + EPS) + acc3 / (s3 + EPS)) + bias[lane];
        out[(size_t)n * 32 + lane] = v;
    }
}

// ---------------- launch ----------------
extern "C" void kernel_launch(void* const* d_in, const int* in_sizes, int n_in,
                              void* d_out, int out_size) {
    const float* x     = (const float*)d_in[0];
    const int*   ei    = (const int*)  d_in[1];
    const float* eattr = (const float*)d_in[2];
    const int*   etype = (const int*)  d_in[3];
    const float* w1  = (const float*)d_in[4];
    const float* q1  = (const float*)d_in[5];
    const float* k1  = (const float*)d_in[6];
    const float* e1  = (const float*)d_in[7];
    const float* le1 = (const float*)d_in[8];
    const float* b1  = (const float*)d_in[9];
    const float* w3  = (const float*)d_in[10];
    const float* q3  = (const float*)d_in[11];
    const float* k3  = (const float*)d_in[12];
    const float* e3  = (const float*)d_in[13];
    const float* le3 = (const float*)d_in[14];
    const float* b3  = (const float*)d_in[15];
    float* out = (float*)d_out;

    const int EB = (EE + 255) / 256;         // 3125
    const int NB = (NN + 255) / 256;         // 196
    const int WF_B = 65536 / 256;            // 256
    const int QKX_B = (NN + 31) / 32;        // 1563
    const dim3 GT((NN + 127) / 128, RR);     // (391, 4)

    k_zero_deg<<<NB, 256>>>();                             // 0
    k_hist<<<EB, 256>>>(ei);                               // 1
    k_wfrag<<<WF_B, 256>>>(w1);                            // 2
    k_gemmt<<<GT, 256>>>(x, 1);                            // 3  <- profile target
    k_scan<<<1, 1024>>>();                                 // 4
    k_scatter<<<EB, 256>>>(ei, etype);                     // 5
    k_M<<<1, 128>>>(le1, e1, le3, e3);                     // 6
    k_wqk<<<16, 256>>>(w1, q1, k1);                        // 7
    k_qkx<<<QKX_B, 256>>>(x, 1);                           // 8
    k_p<<<EB, 256>>>(ei, etype, eattr, 1);                 // 9
    k_agg<<<(NN + 7) / 8, 256>>>(b1, out, 1);              // 10

    k_wfrag<<<WF_B, 256>>>(w3);                            // 11
    k_gemmt<<<GT, 256>>>(x, 2);                            // 12
    k_wqk<<<16, 256>>>(w3, q3, k3);                        // 13
    k_qkx<<<QKX_B, 256>>>(x, 2);                           // 14
    k_p<<<EB, 256>>>(ei, etype, eattr, 2);                 // 15
    k_agg<<<(NN + 7) / 8, 256>>>(b3, out, 2);              // 16
}